// round 2
// baseline (speedup 1.0000x reference)
#include <cuda_runtime.h>
#include <cstdint>

#define B 128
#define L 200
#define D 256
#define V_SIZE 50000

#define COMPUTE_BLOCKS B
#define ZERO_BLOCKS 1024
#define THREADS 256

// Scratch for the weights [B, L] — avoids assuming d_out has a tail region.
__device__ float g_weights[B * L];

// K1: blocks [0,128) compute softmax weights per batch; blocks [128,...) zero w_a.
__global__ void __launch_bounds__(THREADS)
fused_score_softmax_zero(const float* __restrict__ w_es,
                         const float* __restrict__ score_v,
                         float* __restrict__ out,
                         int write_tail)
{
    float* __restrict__ w_a = out;                          // [B, V_SIZE]

    int blk = blockIdx.x;
    int tid = threadIdx.x;

    if (blk >= COMPUTE_BLOCKS) {
        // ---- zero w_a with float4 stores, grid-stride ----
        size_t total4 = ((size_t)B * V_SIZE) / 4;           // 1,600,000
        float4* p = reinterpret_cast<float4*>(w_a);
        size_t idx = (size_t)(blk - COMPUTE_BLOCKS) * THREADS + tid;
        size_t stride = (size_t)ZERO_BLOCKS * THREADS;
        float4 z = make_float4(0.f, 0.f, 0.f, 0.f);
        for (; idx < total4; idx += stride) p[idx] = z;
        return;
    }

    // ---- per-batch scores + softmax ----
    int b = blk;
    __shared__ float sv[D];
    __shared__ float scores[L];
    __shared__ float red[THREADS];

    sv[tid] = score_v[tid];            // D == THREADS == 256
    __syncthreads();

    int wid = tid >> 5;
    int lane = tid & 31;
    const float* base = w_es + (size_t)b * L * D;

    // warp w handles rows w, w+8, ... : coalesced 128B reads per step
    for (int l = wid; l < L; l += 8) {
        const float* row = base + (size_t)l * D;
        float acc = 0.f;
        #pragma unroll
        for (int k = 0; k < D / 32; k++) {
            int d = lane + 32 * k;
            acc = fmaf(row[d], sv[d], acc);
        }
        #pragma unroll
        for (int off = 16; off > 0; off >>= 1)
            acc += __shfl_xor_sync(0xFFFFFFFF, acc, off);
        if (lane == 0) scores[l] = acc;
    }
    __syncthreads();

    // ---- softmax over L=200 ----
    float v = (tid < L) ? scores[tid] : -3.402823466e38f;
    red[tid] = v;
    __syncthreads();
    #pragma unroll
    for (int s = THREADS / 2; s > 0; s >>= 1) {
        if (tid < s) red[tid] = fmaxf(red[tid], red[tid + s]);
        __syncthreads();
    }
    float mx = red[0];
    __syncthreads();

    float e = (tid < L) ? __expf(v - mx) : 0.f;
    red[tid] = e;
    __syncthreads();
    #pragma unroll
    for (int s = THREADS / 2; s > 0; s >>= 1) {
        if (tid < s) red[tid] += red[tid + s];
        __syncthreads();
    }
    float inv = 1.0f / red[0];

    if (tid < L) {
        float w = e * inv;
        g_weights[(size_t)b * L + tid] = w;
        if (write_tail)
            out[(size_t)B * V_SIZE + (size_t)b * L + tid] = w;
    }
}

// K2: one thread per batch, serial scatter in l-order => last-write-wins
// for duplicate vocab indices (matches JAX .at[].set ordering).
// x is int32 (JAX without x64 downcasts int64 -> int32).
__global__ void scatter_kernel(const int* __restrict__ x,
                               float* __restrict__ out)
{
    int b = threadIdx.x;   // 128 threads
    if (b >= B) return;
    float* w_a = out + (size_t)b * V_SIZE;
    const float* w = g_weights + (size_t)b * L;
    const int* xb = x + (size_t)b * L;
    for (int l = 0; l < L; l++) {
        unsigned idx = (unsigned)xb[l];
        if (idx < V_SIZE) w_a[idx] = w[l];
    }
}

extern "C" void kernel_launch(void* const* d_in, const int* in_sizes, int n_in,
                              void* d_out, int out_size)
{
    const float* w_es = (const float*)d_in[0];
    const float* score_v = (const float*)d_in[1];
    const int* x = (const int*)d_in[2];
    float* out = (float*)d_out;

    int write_tail = (out_size >= B * V_SIZE + B * L) ? 1 : 0;

    fused_score_softmax_zero<<<COMPUTE_BLOCKS + ZERO_BLOCKS, THREADS>>>(w_es, score_v, out, write_tail);
    scatter_kernel<<<1, B>>>(x, out);
}

// round 3
// speedup vs baseline: 1.7704x; 1.7704x over previous
#include <cuda_runtime.h>
#include <cstdint>

#define B 128
#define L 200
#define D 256
#define V_SIZE 50000
#define THREADS 256

// One block per batch: zero own w_a row, compute softmax weights,
// then conflict-free parallel scatter (last-occurrence-wins).
__global__ void __launch_bounds__(THREADS)
fused_onehot_kernel(const float* __restrict__ w_es,
                    const float* __restrict__ score_v,
                    const int* __restrict__ x,
                    float* __restrict__ out,
                    int write_tail)
{
    int b = blockIdx.x;
    int tid = threadIdx.x;

    __shared__ float sv[D];
    __shared__ float scores[L];
    __shared__ float red[THREADS];
    __shared__ int   xsh[L];
    __shared__ float wsh[L];

    float* __restrict__ w_a = out + (size_t)b * V_SIZE;

    // ---- Phase A: load score_v + x row to smem, zero own w_a row ----
    sv[tid] = score_v[tid];                       // D == THREADS
    if (tid < L) xsh[tid] = x[(size_t)b * L + tid];

    {
        float4* row4 = reinterpret_cast<float4*>(w_a);   // 50000 % 4 == 0, 16B-aligned
        float4 z = make_float4(0.f, 0.f, 0.f, 0.f);
        #pragma unroll 4
        for (int i = tid; i < V_SIZE / 4; i += THREADS)
            row4[i] = z;
    }
    __syncthreads();

    // ---- Phase B: dot products (warp per row, coalesced) ----
    int wid = tid >> 5;
    int lane = tid & 31;
    const float* base = w_es + (size_t)b * L * D;

    for (int l = wid; l < L; l += 8) {
        const float* row = base + (size_t)l * D;
        float acc = 0.f;
        #pragma unroll
        for (int k = 0; k < D / 32; k++) {
            int d = lane + 32 * k;
            acc = fmaf(row[d], sv[d], acc);
        }
        #pragma unroll
        for (int off = 16; off > 0; off >>= 1)
            acc += __shfl_xor_sync(0xFFFFFFFF, acc, off);
        if (lane == 0) scores[l] = acc;
    }
    __syncthreads();

    // ---- Phase C: softmax over L=200 ----
    float v = (tid < L) ? scores[tid] : -3.402823466e38f;
    red[tid] = v;
    __syncthreads();
    #pragma unroll
    for (int s = THREADS / 2; s > 0; s >>= 1) {
        if (tid < s) red[tid] = fmaxf(red[tid], red[tid + s]);
        __syncthreads();
    }
    float mx = red[0];
    __syncthreads();

    float e = (tid < L) ? __expf(v - mx) : 0.f;
    red[tid] = e;
    __syncthreads();
    #pragma unroll
    for (int s = THREADS / 2; s > 0; s >>= 1) {
        if (tid < s) red[tid] += red[tid + s];
        __syncthreads();
    }
    float inv = 1.0f / red[0];

    if (tid < L) {
        float w = e * inv;
        wsh[tid] = w;
        if (write_tail)
            out[(size_t)B * V_SIZE + (size_t)b * L + tid] = w;
    }
    __syncthreads();   // also orders the Phase-A global zero-stores before scatter

    // ---- Phase D: conflict-free scatter (last occurrence of each index wins) ----
    if (tid < L) {
        int idx = xsh[tid];
        bool last = true;
        for (int l = tid + 1; l < L; l++)
            if (xsh[l] == idx) { last = false; break; }
        if (last && (unsigned)idx < V_SIZE)
            w_a[idx] = wsh[tid];
    }
}

extern "C" void kernel_launch(void* const* d_in, const int* in_sizes, int n_in,
                              void* d_out, int out_size)
{
    const float* w_es = (const float*)d_in[0];
    const float* score_v = (const float*)d_in[1];
    const int* x = (const int*)d_in[2];
    float* out = (float*)d_out;

    int write_tail = (out_size >= B * V_SIZE + B * L) ? 1 : 0;

    fused_onehot_kernel<<<B, THREADS>>>(w_es, score_v, x, out, write_tail);
}

// round 4
// speedup vs baseline: 2.2980x; 1.2980x over previous
#include <cuda_runtime.h>
#include <cstdint>

#define B 128
#define L 200
#define D 256
#define V_SIZE 50000
#define THREADS 256

#define SPLIT 4                     // score blocks per batch
#define ROWS_PER_BLK (L / SPLIT)    // 50
#define SCORE_BLOCKS (B * SPLIT)    // 512
#define ZERO_BLOCKS 1024

__device__ float g_scores[B * L];

// K1: blocks [0,512) compute raw scores (4 blocks per batch, 50 rows each);
//     blocks [512, 512+1024) zero w_a.
__global__ void __launch_bounds__(THREADS)
score_and_zero_kernel(const float* __restrict__ w_es,
                      const float* __restrict__ score_v,
                      float* __restrict__ out)
{
    int blk = blockIdx.x;
    int tid = threadIdx.x;

    if (blk >= SCORE_BLOCKS) {
        // ---- zero w_a [B, V_SIZE] with float4 stores ----
        size_t total4 = ((size_t)B * V_SIZE) / 4;          // 1,600,000
        float4* p = reinterpret_cast<float4*>(out);
        size_t idx = (size_t)(blk - SCORE_BLOCKS) * THREADS + tid;
        size_t stride = (size_t)ZERO_BLOCKS * THREADS;
        float4 z = make_float4(0.f, 0.f, 0.f, 0.f);
        for (; idx < total4; idx += stride) p[idx] = z;
        return;
    }

    // ---- scores: b = blk/SPLIT, rows [chunk*50, chunk*50+50) ----
    int b = blk / SPLIT;
    int l0 = (blk % SPLIT) * ROWS_PER_BLK;

    __shared__ float sv[D];
    sv[tid] = score_v[tid];          // D == THREADS
    __syncthreads();

    int wid = tid >> 5;
    int lane = tid & 31;
    const float* base = w_es + ((size_t)b * L + l0) * D;

    for (int l = wid; l < ROWS_PER_BLK; l += 8) {
        const float* row = base + (size_t)l * D;
        float acc = 0.f;
        #pragma unroll
        for (int k = 0; k < D / 32; k++) {
            int d = lane + 32 * k;
            acc = fmaf(row[d], sv[d], acc);
        }
        #pragma unroll
        for (int off = 16; off > 0; off >>= 1)
            acc += __shfl_xor_sync(0xFFFFFFFF, acc, off);
        if (lane == 0) g_scores[(size_t)b * L + l0 + l] = acc;
    }
}

// K2: one block per batch — softmax + dedup + conflict-free scatter.
__global__ void __launch_bounds__(THREADS)
softmax_scatter_kernel(const int* __restrict__ x,
                       float* __restrict__ out,
                       int write_tail)
{
    int b = blockIdx.x;
    int tid = threadIdx.x;

    __shared__ float red[THREADS];
    __shared__ int   xsh[L];

    if (tid < L) xsh[tid] = x[(size_t)b * L + tid];

    float v = (tid < L) ? g_scores[(size_t)b * L + tid] : -3.402823466e38f;

    // max-reduce
    red[tid] = v;
    __syncthreads();
    #pragma unroll
    for (int s = THREADS / 2; s > 0; s >>= 1) {
        if (tid < s) red[tid] = fmaxf(red[tid], red[tid + s]);
        __syncthreads();
    }
    float mx = red[0];
    __syncthreads();

    // sum-reduce of exp
    float e = (tid < L) ? __expf(v - mx) : 0.f;
    red[tid] = e;
    __syncthreads();
    #pragma unroll
    for (int s = THREADS / 2; s > 0; s >>= 1) {
        if (tid < s) red[tid] += red[tid + s];
        __syncthreads();
    }
    float w = e * (1.0f / red[0]);

    if (tid < L) {
        if (write_tail)
            out[(size_t)B * V_SIZE + (size_t)b * L + tid] = w;

        // last-occurrence-wins: write only if no later duplicate
        int idx = xsh[tid];
        bool last = true;
        for (int l = tid + 1; l < L; l++)
            if (xsh[l] == idx) { last = false; break; }
        if (last && (unsigned)idx < V_SIZE)
            out[(size_t)b * V_SIZE + idx] = w;
    }
}

extern "C" void kernel_launch(void* const* d_in, const int* in_sizes, int n_in,
                              void* d_out, int out_size)
{
    const float* w_es = (const float*)d_in[0];
    const float* score_v = (const float*)d_in[1];
    const int* x = (const int*)d_in[2];
    float* out = (float*)d_out;

    int write_tail = (out_size >= B * V_SIZE + B * L) ? 1 : 0;

    score_and_zero_kernel<<<SCORE_BLOCKS + ZERO_BLOCKS, THREADS>>>(w_es, score_v, out);
    softmax_scatter_kernel<<<B, THREADS>>>(x, out, write_tail);
}

// round 5
// speedup vs baseline: 2.8602x; 1.2447x over previous
#include <cuda_runtime.h>
#include <cstdint>

#define B 128
#define L 200
#define D 256
#define V_SIZE 50000
#define THREADS 256

#define SPLIT 4
#define ROWS_PER_BLK (L / SPLIT)      // 50
#define CHUNK_V (V_SIZE / SPLIT)      // 12500 (divisible by 4)

__device__ float g_scores[B * L];
__device__ int   g_cnt[B];            // zero-init; reset by epilogue each launch

__global__ void __launch_bounds__(THREADS)
fused_all_kernel(const float* __restrict__ w_es,
                 const float* __restrict__ score_v,
                 const int* __restrict__ x,
                 float* __restrict__ out,
                 int write_tail)
{
    int blk = blockIdx.x;
    int tid = threadIdx.x;
    int b = blk >> 2;                 // batch
    int c = blk & 3;                  // chunk

    __shared__ float sv[D];
    __shared__ int   s_islast;

    sv[tid] = score_v[tid];           // D == THREADS
    __syncthreads();

    // ---- Phase A: zero my quarter of w_a[b] ----
    {
        float4* p = reinterpret_cast<float4*>(out + (size_t)b * V_SIZE + (size_t)c * CHUNK_V);
        float4 z = make_float4(0.f, 0.f, 0.f, 0.f);
        #pragma unroll
        for (int i = tid; i < CHUNK_V / 4; i += THREADS)   // 3125 float4
            p[i] = z;
    }

    // ---- Phase B: 50 dot products (warp per row, float4 loads) ----
    {
        int wid = tid >> 5;
        int lane = tid & 31;
        int l0 = c * ROWS_PER_BLK;
        const float* base = w_es + ((size_t)b * L + l0) * D;
        const float4* sv4 = reinterpret_cast<const float4*>(sv);

        for (int l = wid; l < ROWS_PER_BLK; l += 8) {
            const float4* row4 = reinterpret_cast<const float4*>(base + (size_t)l * D);
            float acc = 0.f;
            #pragma unroll
            for (int k = 0; k < 2; k++) {
                int d = lane + 32 * k;
                float4 a = row4[d];
                float4 s = sv4[d];
                acc = fmaf(a.x, s.x, acc);
                acc = fmaf(a.y, s.y, acc);
                acc = fmaf(a.z, s.z, acc);
                acc = fmaf(a.w, s.w, acc);
            }
            #pragma unroll
            for (int off = 16; off > 0; off >>= 1)
                acc += __shfl_xor_sync(0xFFFFFFFF, acc, off);
            if (lane == 0) g_scores[(size_t)b * L + l0 + l] = acc;
        }
    }

    // ---- Phase C: last block for this batch does the epilogue ----
    __threadfence();                  // make zeroes + scores visible
    __syncthreads();
    if (tid == 0) {
        int old = atomicAdd(&g_cnt[b], 1);
        s_islast = (old == 3);
    }
    __syncthreads();
    if (!s_islast) return;
    __threadfence();                  // acquire: see peers' zeroes + scores

    // ---- Epilogue: softmax + dedup scatter for batch b ----
    __shared__ float red[8];
    __shared__ int   xsh[L];
    __shared__ float wsh[L];

    if (tid < L) xsh[tid] = x[(size_t)b * L + tid];

    float v = (tid < L) ? g_scores[(size_t)b * L + tid] : -3.402823466e38f;

    int wid = tid >> 5;
    int lane = tid & 31;

    // block max via warp shuffles
    float m = v;
    #pragma unroll
    for (int off = 16; off > 0; off >>= 1)
        m = fmaxf(m, __shfl_xor_sync(0xFFFFFFFF, m, off));
    if (lane == 0) red[wid] = m;
    __syncthreads();
    m = red[lane & 7];
    #pragma unroll
    for (int off = 4; off > 0; off >>= 1)
        m = fmaxf(m, __shfl_xor_sync(0xFFFFFFFF, m, off));
    float mx = __shfl_sync(0xFFFFFFFF, m, 0);
    mx = __shfl_sync(0xFFFFFFFF, mx, 0);   // uniform within warp; need block-uniform:
    // recompute block-uniform max via smem (cheap, avoids cross-warp shfl subtlety)
    if (tid == 0) {
        float t = red[0];
        #pragma unroll
        for (int i = 1; i < 8; i++) t = fmaxf(t, red[i]);
        red[0] = t;
    }
    __syncthreads();
    mx = red[0];
    __syncthreads();

    // block sum of exp
    float e = (tid < L) ? __expf(v - mx) : 0.f;
    float s = e;
    #pragma unroll
    for (int off = 16; off > 0; off >>= 1)
        s += __shfl_xor_sync(0xFFFFFFFF, s, off);
    if (lane == 0) red[wid] = s;
    __syncthreads();
    if (tid == 0) {
        float t = 0.f;
        #pragma unroll
        for (int i = 0; i < 8; i++) t += red[i];
        red[0] = 1.0f / t;
    }
    __syncthreads();
    float inv = red[0];

    float w = e * inv;
    if (tid < L) wsh[tid] = w;
    __syncthreads();

    if (tid < L) {
        if (write_tail)
            out[(size_t)B * V_SIZE + (size_t)b * L + tid] = w;

        // branchless last-occurrence check (pipelined LDS, no dependent branch)
        int idx = xsh[tid];
        int last = 1;
        #pragma unroll 8
        for (int l = tid + 1; l < L; l++)
            last &= (xsh[l] != idx);
        if (last && (unsigned)idx < V_SIZE)
            out[(size_t)b * V_SIZE + idx] = wsh[tid];
    }

    // reset counter for next graph replay
    if (tid == 0) g_cnt[b] = 0;
}

extern "C" void kernel_launch(void* const* d_in, const int* in_sizes, int n_in,
                              void* d_out, int out_size)
{
    const float* w_es = (const float*)d_in[0];
    const float* score_v = (const float*)d_in[1];
    const int* x = (const int*)d_in[2];
    float* out = (float*)d_out;

    int write_tail = (out_size >= B * V_SIZE + B * L) ? 1 : 0;

    fused_all_kernel<<<B * SPLIT, THREADS>>>(w_es, score_v, x, out, write_tail);
}

// round 6
// speedup vs baseline: 3.2445x; 1.1344x over previous
#include <cuda_runtime.h>
#include <cstdint>

#define B 128
#define L 200
#define D 256
#define V_SIZE 50000
#define THREADS 256

#define SPLIT 4                     // score blocks per batch
#define ROWS_PER_BLK (L / SPLIT)    // 50
#define SCORE_BLOCKS (B * SPLIT)    // 512
#define ZERO_BLOCKS 1024

__device__ float g_scores[B * L];

// K1 (unchanged from R4, proven ~8.2us): blocks [0,512) compute raw scores;
// blocks [512, 1536) zero w_a with float4 stores.
__global__ void __launch_bounds__(THREADS)
score_and_zero_kernel(const float* __restrict__ w_es,
                      const float* __restrict__ score_v,
                      float* __restrict__ out)
{
    int blk = blockIdx.x;
    int tid = threadIdx.x;

    if (blk >= SCORE_BLOCKS) {
        size_t total4 = ((size_t)B * V_SIZE) / 4;          // 1,600,000
        float4* p = reinterpret_cast<float4*>(out);
        size_t idx = (size_t)(blk - SCORE_BLOCKS) * THREADS + tid;
        size_t stride = (size_t)ZERO_BLOCKS * THREADS;
        float4 z = make_float4(0.f, 0.f, 0.f, 0.f);
        for (; idx < total4; idx += stride) p[idx] = z;
        return;
    }

    int b = blk / SPLIT;
    int l0 = (blk % SPLIT) * ROWS_PER_BLK;

    __shared__ float sv[D];
    sv[tid] = score_v[tid];          // D == THREADS
    __syncthreads();

    int wid = tid >> 5;
    int lane = tid & 31;
    const float* base = w_es + ((size_t)b * L + l0) * D;
    const float4* sv4 = reinterpret_cast<const float4*>(sv);

    for (int l = wid; l < ROWS_PER_BLK; l += 8) {
        const float4* row4 = reinterpret_cast<const float4*>(base + (size_t)l * D);
        float acc = 0.f;
        #pragma unroll
        for (int k = 0; k < 2; k++) {
            int d = lane + 32 * k;
            float4 a = row4[d];
            float4 s = sv4[d];
            acc = fmaf(a.x, s.x, acc);
            acc = fmaf(a.y, s.y, acc);
            acc = fmaf(a.z, s.z, acc);
            acc = fmaf(a.w, s.w, acc);
        }
        #pragma unroll
        for (int off = 16; off > 0; off >>= 1)
            acc += __shfl_xor_sync(0xFFFFFFFF, acc, off);
        if (lane == 0) g_scores[(size_t)b * L + l0 + l] = acc;
    }
}

// K2: latency-minimal softmax + branchless dedup + conflict-free scatter.
__global__ void __launch_bounds__(THREADS)
softmax_scatter_kernel(const int* __restrict__ x,
                       float* __restrict__ out,
                       int write_tail)
{
    int b = blockIdx.x;
    int tid = threadIdx.x;
    int wid = tid >> 5;
    int lane = tid & 31;

    __shared__ int   xsh[THREADS];
    __shared__ float redm[8];
    __shared__ float reds[8];

    // Front-load both gmem reads so their latencies overlap.
    int   xv = (tid < L) ? x[(size_t)b * L + tid] : -1;
    float v  = (tid < L) ? g_scores[(size_t)b * L + tid] : -3.402823466e38f;
    xsh[tid] = xv;
    __syncthreads();

    // Branchless last-occurrence check (pipelined LDS, no dependent branch).
    int last = 1;
    #pragma unroll 8
    for (int l = tid + 1; l < L; l++)
        last &= (xsh[l] != xv);

    // Block max: warp shuffle -> 8-entry smem -> broadcast read (1 barrier).
    float m = v;
    #pragma unroll
    for (int off = 16; off > 0; off >>= 1)
        m = fmaxf(m, __shfl_xor_sync(0xFFFFFFFF, m, off));
    if (lane == 0) redm[wid] = m;
    __syncthreads();
    float mx = redm[0];
    #pragma unroll
    for (int i = 1; i < 8; i++) mx = fmaxf(mx, redm[i]);

    // Block sum of exp: same pattern (1 barrier).
    float e = (tid < L) ? __expf(v - mx) : 0.f;
    float s = e;
    #pragma unroll
    for (int off = 16; off > 0; off >>= 1)
        s += __shfl_xor_sync(0xFFFFFFFF, s, off);
    if (lane == 0) reds[wid] = s;
    __syncthreads();
    float tot = reds[0];
    #pragma unroll
    for (int i = 1; i < 8; i++) tot += reds[i];

    float w = e * (1.0f / tot);

    if (tid < L) {
        if (write_tail)
            out[(size_t)B * V_SIZE + (size_t)b * L + tid] = w;
        if (last && (unsigned)xv < V_SIZE)
            out[(size_t)b * V_SIZE + xv] = w;
    }
}

extern "C" void kernel_launch(void* const* d_in, const int* in_sizes, int n_in,
                              void* d_out, int out_size)
{
    const float* w_es = (const float*)d_in[0];
    const float* score_v = (const float*)d_in[1];
    const int* x = (const int*)d_in[2];
    float* out = (float*)d_out;

    int write_tail = (out_size >= B * V_SIZE + B * L) ? 1 : 0;

    score_and_zero_kernel<<<SCORE_BLOCKS + ZERO_BLOCKS, THREADS>>>(w_es, score_v, out);
    softmax_scatter_kernel<<<B, THREADS>>>(x, out, write_tail);
}